// round 16
// baseline (speedup 1.0000x reference)
#include <cuda_runtime.h>
#include <cuda_bf16.h>
#include <cstdint>

// ===========================================================================
// VisionExperts via mma.sync bf16 3-pass split (AhBh + AhBl + AlBh, fp32 acc)
// cp.async -> SW128 smem (3-stage) -> ldmatrix -> HMMA.16816, 512 thr/16 warps.
// R8 architecture (separate projector GEMMs, RMW out) + vectorized prep and
// E1 resize fused into its im2col.
// ===========================================================================

// ---------------- device scratch (globals; no runtime alloc) ----------------
__device__ __nv_bfloat16 g_patch_h[41943040];     //  84 MB   [M, Kpad]
__device__ __nv_bfloat16 g_patch_l[41943040];     //  84 MB
__device__ __nv_bfloat16 g_featA_h[75497472];     // 151 MB   [65536, c]
__device__ __nv_bfloat16 g_featA_l[75497472];     // 151 MB
__device__ float         g_feat[28311552];        // 113 MB   tower fp32 out (E1/E2)
__device__ __nv_bfloat16 g_wT_h[3538944];         //   7 MB   [N, Kpad]
__device__ __nv_bfloat16 g_wT_l[3538944];
__device__ float         g_w[192];                // routing weight [expert][b]

// ---------------- helpers ----------------
__device__ __forceinline__ uint32_t smem_u32(const void* p) {
    uint32_t a;
    asm("{ .reg .u64 t; cvta.to.shared.u64 t, %1; cvt.u32.u64 %0, t; }" : "=r"(a) : "l"(p));
    return a;
}
#define CP_ASYNC16(saddr, gptr) \
    asm volatile("cp.async.cg.shared.global [%0], [%1], 16;" :: "r"(saddr), "l"(gptr))
#define CP_COMMIT() asm volatile("cp.async.commit_group;" ::: "memory")
#define LDSM4(d0, d1, d2, d3, addr) \
    asm volatile("ldmatrix.sync.aligned.m8n8.x4.shared.b16 {%0,%1,%2,%3}, [%4];" \
                 : "=r"(d0), "=r"(d1), "=r"(d2), "=r"(d3) : "r"(addr))
#define MMA16816(d, a, b) \
    asm volatile("mma.sync.aligned.m16n8k16.row.col.f32.bf16.bf16.f32 " \
                 "{%0,%1,%2,%3}, {%4,%5,%6,%7}, {%8,%9}, {%0,%1,%2,%3};" \
                 : "+f"((d)[0]), "+f"((d)[1]), "+f"((d)[2]), "+f"((d)[3]) \
                 : "r"((a)[0]), "r"((a)[1]), "r"((a)[2]), "r"((a)[3]), \
                   "r"((b)[0]), "r"((b)[1]))

#define SW128(o) ((o) ^ (((o) >> 3) & 0x70))

__device__ __forceinline__ void split2(float v, __nv_bfloat16& h, __nv_bfloat16& l) {
    h = __float2bfloat16(v);
    l = __float2bfloat16(v - __bfloat162float(h));
}

// ---------------- small kernels ----------------
__global__ void compute_weights_kernel(const int* __restrict__ sel,
                                       const float* __restrict__ rw) {
    int i = threadIdx.x;
    if (i < 192) {
        int e = i / 64, b = i % 64;
        float w = 0.0f;
        if (sel[2 * b + 0] == e) w += rw[2 * b + 0];
        if (sel[2 * b + 1] == e) w += rw[2 * b + 1];
        g_w[i] = w;
    }
}

// im2col + bf16 split, 2 k-elements per thread (p even -> pairs never cross rows)
__global__ void im2col_split_kernel(const float* __restrict__ src,
                                    __nv_bfloat162* __restrict__ dh,
                                    __nv_bfloat162* __restrict__ dl,
                                    int g, int p, int s, int Kpad, int expert) {
    long long idx = (long long)blockIdx.x * blockDim.x + threadIdx.x;
    int K2 = Kpad >> 1;
    long long total = 64LL * g * g * K2;
    if (idx >= total) return;
    int k = ((int)(idx % K2)) << 1;
    long long t = idx / K2;
    int token = (int)(t % (g * g));
    int b = (int)(t / (g * g));
    if (g_w[expert * 64 + b] == 0.0f) return;
    float2 v = make_float2(0.0f, 0.0f);
    int K = 3 * p * p;
    if (k < K) {
        int ch = k / (p * p);
        int r = k % (p * p);
        int py = r / p, px = r % p;
        int gy = token / g, gx = token % g;
        v = *(const float2*)(src + (((size_t)b * 3 + ch) * s + (gy * p + py)) * s
                             + (gx * p + px));
    }
    __nv_bfloat16 h0, l0, h1, l1;
    split2(v.x, h0, l0); split2(v.y, h1, l1);
    __nv_bfloat162 ph; ph.x = h0; ph.y = h1;
    __nv_bfloat162 pl; pl.x = l0; pl.y = l1;
    dh[idx] = ph; dl[idx] = pl;
}

// E1: fused 448->336 bilinear resize + im2col + bf16 split (2 k-elems/thread)
__global__ void im2col_resize_split_kernel(const float* __restrict__ x,
                                           __nv_bfloat162* __restrict__ dh,
                                           __nv_bfloat162* __restrict__ dl) {
    long long idx = (long long)blockIdx.x * blockDim.x + threadIdx.x;
    const int K2 = 320;                       // Kpad 640 / 2
    long long total = 64LL * 576 * K2;
    if (idx >= total) return;
    int k = ((int)(idx % K2)) << 1;
    long long t = idx / K2;
    int token = (int)(t % 576);
    int b = (int)(t / 576);
    if (g_w[64 + b] == 0.0f) return;
    float v0 = 0.0f, v1 = 0.0f;
    if (k < 588) {
        int ch = k / 196;
        int r = k % 196;
        int py = r / 14, px = r % 14;
        int gy = token / 24, gx = token % 24;
        int oy = gy * 14 + py;
        int ox = gx * 14 + px;
        const float scale = 447.0f / 335.0f;
        float fy = oy * scale;
        int y0 = (int)floorf(fy); int y1 = min(y0 + 1, 447);
        float ty = fy - (float)y0;
        const float* img = x + (size_t)(b * 3 + ch) * 448 * 448;
        const float* r0p = img + (size_t)y0 * 448;
        const float* r1p = img + (size_t)y1 * 448;
#pragma unroll
        for (int j = 0; j < 2; ++j) {
            float fx = (ox + j) * scale;
            int x0 = (int)floorf(fx); int x1 = min(x0 + 1, 447);
            float tx = fx - (float)x0;
            float a0 = r0p[x0] + (r0p[x1] - r0p[x0]) * tx;
            float a1 = r1p[x0] + (r1p[x1] - r1p[x0]) * tx;
            float v = a0 + (a1 - a0) * ty;
            if (j == 0) v0 = v; else v1 = v;
        }
    }
    __nv_bfloat16 h0, l0, h1, l1;
    split2(v0, h0, l0); split2(v1, h1, l1);
    __nv_bfloat162 ph; ph.x = h0; ph.y = h1;
    __nv_bfloat162 pl; pl.x = l0; pl.y = l1;
    dh[idx] = ph; dl[idx] = pl;
}

// w[K,N] -> wT[N,Kpad] (zero pad) + bf16 split, 32x32 smem tiles
__global__ void transpose_split_kernel(const float* __restrict__ w,
                                       __nv_bfloat16* __restrict__ th,
                                       __nv_bfloat16* __restrict__ tl,
                                       int K, int N, int Kpad) {
    __shared__ float t[32][33];
    int k0 = blockIdx.y * 32, n0 = blockIdx.x * 32;
    int kk = k0 + threadIdx.y, nn = n0 + threadIdx.x;
    t[threadIdx.y][threadIdx.x] = (kk < K && nn < N) ? w[(size_t)kk * N + nn] : 0.0f;
    __syncthreads();
    int on = n0 + threadIdx.y, ok = k0 + threadIdx.x;
    if (on < N && ok < Kpad) {
        __nv_bfloat16 h, l; split2(t[threadIdx.x][threadIdx.y], h, l);
        th[(size_t)on * Kpad + ok] = h;
        tl[(size_t)on * Kpad + ok] = l;
    }
}

// feature grid resize g x g -> 32 x 32 with bf16 split output (2-wide)
__global__ void feat_resize_split_kernel(const float* __restrict__ in,
                                         __nv_bfloat16* __restrict__ oh,
                                         __nv_bfloat16* __restrict__ ol,
                                         int g, int c, int expert) {
    int token = blockIdx.x & 1023;
    int b = blockIdx.x >> 10;
    if (g_w[expert * 64 + b] == 0.0f) return;
    int oy = token >> 5, ox = token & 31;
    float scale = (float)(g - 1) / 31.0f;
    float fy = oy * scale, fx = ox * scale;
    int y0 = (int)floorf(fy), x0 = (int)floorf(fx);
    int y1 = min(y0 + 1, g - 1), x1 = min(x0 + 1, g - 1);
    float ty = fy - y0, tx = fx - x0;
    float w00 = (1.f - ty) * (1.f - tx), w01 = (1.f - ty) * tx;
    float w10 = ty * (1.f - tx),         w11 = ty * tx;
    const float* base = in + (size_t)b * g * g * c;
    const float2* p00 = (const float2*)(base + (size_t)(y0 * g + x0) * c);
    const float2* p01 = (const float2*)(base + (size_t)(y0 * g + x1) * c);
    const float2* p10 = (const float2*)(base + (size_t)(y1 * g + x0) * c);
    const float2* p11 = (const float2*)(base + (size_t)(y1 * g + x1) * c);
    size_t rowOff = ((size_t)b * 1024 + token) * c;
    __nv_bfloat162* ph2 = (__nv_bfloat162*)(oh + rowOff);
    __nv_bfloat162* pl2 = (__nv_bfloat162*)(ol + rowOff);
    int c2 = c >> 1;
    for (int i = threadIdx.x; i < c2; i += blockDim.x) {
        float2 a = p00[i], bq = p01[i], cq = p10[i], d = p11[i];
        float v0 = w00 * a.x + w01 * bq.x + w10 * cq.x + w11 * d.x;
        float v1 = w00 * a.y + w01 * bq.y + w10 * cq.y + w11 * d.y;
        __nv_bfloat16 h0, l0, h1, l1;
        split2(v0, h0, l0); split2(v1, h1, l1);
        __nv_bfloat162 ph; ph.x = h0; ph.y = h1;
        __nv_bfloat162 pl; pl.x = l0; pl.y = l1;
        ph2[i] = ph; pl2[i] = pl;
    }
}

// ===========================================================================
// mma.sync GEMM: D[128x128] = (Ah+Al)[128,K] @ (Bh+Bl)[128,K]^T (3 passes).
// SW128 smem stages of BK=64 (Ah|Al|Bh|Bl @ 16KB each), 3-stage pipeline.
// 512 threads, 16 warps, warp tile 32x32 (warp grid 4x4).
// MODE 0: tower -> split bf16 (Ch/Cl, ldc)    MODE 1: tower -> fp32 (C, ldc)
// MODE 2: proj  -> C[row*1024+col] += w_b * (v + bias)
// ===========================================================================
#define STAGE_BYTES 65536
#define NSTAGE 3

__device__ __forceinline__ void load_stage(
    uint32_t sb, const __nv_bfloat16* Ah, const __nv_bfloat16* Al,
    const __nv_bfloat16* Bh, const __nv_bfloat16* Bl,
    int rowStart, int colStart, int Kpad, int k0, int tid) {
#pragma unroll 8
    for (int c = tid; c < 4096; c += 512) {
        int half = (c >> 10) & 1;
        int cc = c & 1023;
        int r = cc >> 3, kc = cc & 7;
        const __nv_bfloat16* gp;
        uint32_t so;
        if (c < 2048) {
            gp = (half ? Al : Ah) + (size_t)(rowStart + r) * Kpad + k0 + kc * 8;
            so = sb + half * 16384 + SW128(r * 128 + kc * 16);
        } else {
            gp = (half ? Bl : Bh) + (size_t)(colStart + r) * Kpad + k0 + kc * 8;
            so = sb + 32768 + half * 16384 + SW128(r * 128 + kc * 16);
        }
        CP_ASYNC16(so, (const void*)gp);
    }
}

template <int MODE>
__global__ __launch_bounds__(512, 1) void gemm_mma(
    int Kpad, int tps, int expert,
    const __nv_bfloat16* __restrict__ Ah, const __nv_bfloat16* __restrict__ Al,
    const __nv_bfloat16* __restrict__ Bh, const __nv_bfloat16* __restrict__ Bl,
    const float* __restrict__ bias,
    float* __restrict__ C, __nv_bfloat16* __restrict__ Ch, __nv_bfloat16* __restrict__ Cl,
    int ldc) {
    const int tid = threadIdx.x;
    const int wid = tid >> 5, lane = tid & 31;
    const int rowStart = blockIdx.y * 128;
    const int colStart = blockIdx.x * 128;

    // routing skip: all samples covered by this M-block unrouted -> no work
    {
        int bLo = rowStart / tps, bHi = (rowStart + 127) / tps;
        bool any = false;
        for (int b = bLo; b <= bHi; ++b) any = any || (g_w[expert * 64 + b] != 0.0f);
        if (!any) return;
    }

    extern __shared__ __align__(1024) char smem[];
    const uint32_t sb0 = smem_u32(smem);
    const int wm = (wid >> 2) * 32, wn = (wid & 3) * 32;

    float acc[2][4][4];
#pragma unroll
    for (int i = 0; i < 2; ++i)
#pragma unroll
        for (int j = 0; j < 4; ++j)
#pragma unroll
            for (int r = 0; r < 4; ++r) acc[i][j][r] = 0.0f;

    const int KBn = Kpad >> 6;
    const int arow = wm + (lane & 15);
    const int alo  = lane >> 4;
    const int bmat = lane >> 3;
    const int brow = ((bmat >> 1) << 3) + (lane & 7);
    const int bko  = bmat & 1;

    load_stage(sb0, Ah, Al, Bh, Bl, rowStart, colStart, Kpad, 0, tid);
    CP_COMMIT();
    if (KBn > 1) {
        load_stage(sb0 + STAGE_BYTES, Ah, Al, Bh, Bl, rowStart, colStart, Kpad, 64, tid);
        CP_COMMIT();
    }

    int stage = 0;
    for (int kb = 0; kb < KBn; ++kb) {
        if (kb + 1 < KBn)
            asm volatile("cp.async.wait_group 1;" ::: "memory");
        else
            asm volatile("cp.async.wait_group 0;" ::: "memory");
        __syncthreads();

        const uint32_t sb = sb0 + stage * STAGE_BYTES;
#pragma unroll
        for (int kk = 0; kk < 4; ++kk) {
            uint32_t ah[2][4], al[2][4], bh[4][2], bl[4][2];
#pragma unroll
            for (int mi = 0; mi < 2; ++mi) {
                uint32_t off = SW128((arow + 16 * mi) * 128 + (kk * 2 + alo) * 16);
                LDSM4(ah[mi][0], ah[mi][1], ah[mi][2], ah[mi][3], sb + off);
                LDSM4(al[mi][0], al[mi][1], al[mi][2], al[mi][3], sb + 16384 + off);
            }
#pragma unroll
            for (int p = 0; p < 2; ++p) {
                uint32_t off = SW128((wn + p * 16 + brow) * 128 + (kk * 2 + bko) * 16);
                LDSM4(bh[2 * p][0], bh[2 * p][1], bh[2 * p + 1][0], bh[2 * p + 1][1],
                      sb + 32768 + off);
                LDSM4(bl[2 * p][0], bl[2 * p][1], bl[2 * p + 1][0], bl[2 * p + 1][1],
                      sb + 49152 + off);
            }
#pragma unroll
            for (int mi = 0; mi < 2; ++mi)
#pragma unroll
                for (int nj = 0; nj < 4; ++nj) {
                    MMA16816(acc[mi][nj], ah[mi], bh[nj]);
                    MMA16816(acc[mi][nj], ah[mi], bl[nj]);
                    MMA16816(acc[mi][nj], al[mi], bh[nj]);
                }
        }

        if (kb + 2 < KBn) {
            int ns = stage + 2; if (ns >= NSTAGE) ns -= NSTAGE;
            load_stage(sb0 + ns * STAGE_BYTES, Ah, Al, Bh, Bl,
                       rowStart, colStart, Kpad, (kb + 2) << 6, tid);
            CP_COMMIT();
        }
        if (++stage == NSTAGE) stage = 0;
    }

    // -------- epilogue straight from registers --------
    const int tq = lane >> 2;            // row within 8
    const int tr2 = (lane & 3) * 2;      // col pair
    if (MODE == 2) {
        float w = g_w[expert * 64 + (rowStart >> 10)];
#pragma unroll
        for (int nj = 0; nj < 4; ++nj) {
            int col = colStart + wn + nj * 8 + tr2;
            float b0 = bias[col], b1 = bias[col + 1];
#pragma unroll
            for (int mi = 0; mi < 2; ++mi) {
                int row0 = rowStart + wm + mi * 16 + tq;
                float* p0 = C + (size_t)row0 * 1024 + col;
                float* p1 = p0 + 8 * 1024;
                p0[0] += w * (acc[mi][nj][0] + b0);
                p0[1] += w * (acc[mi][nj][1] + b1);
                p1[0] += w * (acc[mi][nj][2] + b0);
                p1[1] += w * (acc[mi][nj][3] + b1);
            }
        }
    } else if (MODE == 0) {
#pragma unroll
        for (int nj = 0; nj < 4; ++nj) {
            int col = colStart + wn + nj * 8 + tr2;
            float b0 = bias[col], b1 = bias[col + 1];
#pragma unroll
            for (int mi = 0; mi < 2; ++mi) {
                int row0 = rowStart + wm + mi * 16 + tq;
#pragma unroll
                for (int h = 0; h < 2; ++h) {
                    int row = row0 + h * 8;
                    float v0 = acc[mi][nj][2 * h + 0] + b0;
                    float v1 = acc[mi][nj][2 * h + 1] + b1;
                    __nv_bfloat16 h0, l0, h1, l1;
                    split2(v0, h0, l0); split2(v1, h1, l1);
                    __nv_bfloat162 ph; ph.x = h0; ph.y = h1;
                    __nv_bfloat162 pl; pl.x = l0; pl.y = l1;
                    *(__nv_bfloat162*)(Ch + (size_t)row * ldc + col) = ph;
                    *(__nv_bfloat162*)(Cl + (size_t)row * ldc + col) = pl;
                }
            }
        }
    } else {
#pragma unroll
        for (int nj = 0; nj < 4; ++nj) {
            int col = colStart + wn + nj * 8 + tr2;
            float b0 = bias[col], b1 = bias[col + 1];
#pragma unroll
            for (int mi = 0; mi < 2; ++mi) {
                int row0 = rowStart + wm + mi * 16 + tq;
                float* p0 = C + (size_t)row0 * ldc + col;
                float* p1 = p0 + (size_t)8 * ldc;
                p0[0] = acc[mi][nj][0] + b0;
                p0[1] = acc[mi][nj][1] + b1;
                p1[0] = acc[mi][nj][2] + b0;
                p1[1] = acc[mi][nj][3] + b1;
            }
        }
    }
}

// ===========================================================================
extern "C" void kernel_launch(void* const* d_in, const int* in_sizes, int n_in,
                              void* d_out, int out_size) {
    const float* x   = (const float*)d_in[0];
    const int*   sel = (const int*)d_in[1];
    const float* rw  = (const float*)d_in[2];
    const float* wt0 = (const float*)d_in[3];
    const float* bt0 = (const float*)d_in[4];
    const float* wp0 = (const float*)d_in[5];
    const float* bp0 = (const float*)d_in[6];
    const float* wt1 = (const float*)d_in[7];
    const float* bt1 = (const float*)d_in[8];
    const float* wp1 = (const float*)d_in[9];
    const float* bp1 = (const float*)d_in[10];
    const float* wt2 = (const float*)d_in[11];
    const float* bt2 = (const float*)d_in[12];
    const float* wp2 = (const float*)d_in[13];
    const float* bp2 = (const float*)d_in[14];
    float* out = (float*)d_out;

    float* pfeat;
    __nv_bfloat16 *pph, *ppl, *pfh, *pfl, *pwh, *pwl;
    cudaGetSymbolAddress((void**)&pph, g_patch_h);
    cudaGetSymbolAddress((void**)&ppl, g_patch_l);
    cudaGetSymbolAddress((void**)&pfh, g_featA_h);
    cudaGetSymbolAddress((void**)&pfl, g_featA_l);
    cudaGetSymbolAddress((void**)&pfeat, g_feat);
    cudaGetSymbolAddress((void**)&pwh, g_wT_h);
    cudaGetSymbolAddress((void**)&pwl, g_wT_l);

    const int SMEM = NSTAGE * STAGE_BYTES;   // 196608
    cudaFuncSetAttribute(gemm_mma<0>, cudaFuncAttributeMaxDynamicSharedMemorySize, SMEM);
    cudaFuncSetAttribute(gemm_mma<1>, cudaFuncAttributeMaxDynamicSharedMemorySize, SMEM);
    cudaFuncSetAttribute(gemm_mma<2>, cudaFuncAttributeMaxDynamicSharedMemorySize, SMEM);

    compute_weights_kernel<<<1, 192>>>(sel, rw);
    cudaMemsetAsync(d_out, 0, (size_t)out_size * sizeof(float), 0);

    // ---------------- Expert 0: g=32 c=1024, Ktower 588->640 ----------------
    {
        long long tot2 = 64LL * 1024 * 320;
        im2col_split_kernel<<<(unsigned)((tot2 + 255) / 256), 256>>>(
            x, (__nv_bfloat162*)pph, (__nv_bfloat162*)ppl, 32, 14, 448, 640, 0);
        transpose_split_kernel<<<dim3(32, 20), dim3(32, 32)>>>(wt0, pwh, pwl, 588, 1024, 640);
        gemm_mma<0><<<dim3(8, 512), 512, SMEM>>>(640, 1024, 0,
            pph, ppl, pwh, pwl, bt0, nullptr, pfh, pfl, 1024);
        transpose_split_kernel<<<dim3(32, 32), dim3(32, 32)>>>(wp0, pwh, pwl, 1024, 1024, 1024);
        gemm_mma<2><<<dim3(8, 512), 512, SMEM>>>(1024, 1024, 0,
            pfh, pfl, pwh, pwl, bp0, out, nullptr, nullptr, 1024);
    }

    // ---------------- Expert 1: g=24 c=768, fused resize+im2col ----------------
    {
        long long tot2 = 64LL * 576 * 320;
        im2col_resize_split_kernel<<<(unsigned)((tot2 + 255) / 256), 256>>>(
            x, (__nv_bfloat162*)pph, (__nv_bfloat162*)ppl);
        transpose_split_kernel<<<dim3(24, 20), dim3(32, 32)>>>(wt1, pwh, pwl, 588, 768, 640);
        gemm_mma<1><<<dim3(6, 288), 512, SMEM>>>(640, 576, 1,
            pph, ppl, pwh, pwl, bt1, pfeat, nullptr, nullptr, 768);
        feat_resize_split_kernel<<<64 * 1024, 128>>>(pfeat, pfh, pfl, 24, 768, 1);
        transpose_split_kernel<<<dim3(32, 24), dim3(32, 32)>>>(wp1, pwh, pwl, 768, 1024, 768);
        gemm_mma<2><<<dim3(8, 512), 512, SMEM>>>(768, 1024, 1,
            pfh, pfl, pwh, pwl, bp1, out, nullptr, nullptr, 1024);
    }

    // ---------------- Expert 2: g=14 c=1152, Ktower=3072 ----------------
    {
        long long tot2 = 64LL * 196 * 1536;
        im2col_split_kernel<<<(unsigned)((tot2 + 255) / 256), 256>>>(
            x, (__nv_bfloat162*)pph, (__nv_bfloat162*)ppl, 14, 32, 448, 3072, 2);
        transpose_split_kernel<<<dim3(36, 96), dim3(32, 32)>>>(wt2, pwh, pwl, 3072, 1152, 3072);
        gemm_mma<1><<<dim3(9, 98), 512, SMEM>>>(3072, 196, 2,
            pph, ppl, pwh, pwl, bt2, pfeat, nullptr, nullptr, 1152);
        feat_resize_split_kernel<<<64 * 1024, 128>>>(pfeat, pfh, pfl, 14, 1152, 2);
        transpose_split_kernel<<<dim3(32, 36), dim3(32, 32)>>>(wp2, pwh, pwl, 1152, 1024, 1152);
        gemm_mma<2><<<dim3(8, 512), 512, SMEM>>>(1152, 1024, 2,
            pfh, pfl, pwh, pwl, bp2, out, nullptr, nullptr, 1024);
    }
}

// round 17
// speedup vs baseline: 1.5374x; 1.5374x over previous
#include <cuda_runtime.h>
#include <cuda_bf16.h>
#include <cstdint>

// ===========================================================================
// VisionExperts via mma.sync bf16 3-pass split (AhBh + AhBl + AlBh, fp32 acc)
// cp.async -> SW128 smem (3-stage) -> ldmatrix -> HMMA.16816, 512 thr/16 warps.
// Pass-major MMA emission: dependent accumulator updates separated by 8
// independent MMAs to hide HMMA latency.
// ===========================================================================

// ---------------- device scratch (globals; no runtime alloc) ----------------
__device__ __nv_bfloat16 g_patch_h[41943040];     //  84 MB   [M, Kpad]
__device__ __nv_bfloat16 g_patch_l[41943040];     //  84 MB
__device__ __nv_bfloat16 g_featA_h[75497472];     // 151 MB   [65536, c]
__device__ __nv_bfloat16 g_featA_l[75497472];     // 151 MB
__device__ float         g_feat[28311552];        // 113 MB   tower fp32 out (E1/E2)
__device__ __nv_bfloat16 g_wT_h[3538944];         //   7 MB   [N, Kpad]
__device__ __nv_bfloat16 g_wT_l[3538944];
__device__ float         g_w[192];                // routing weight [expert][b]

// ---------------- helpers ----------------
__device__ __forceinline__ uint32_t smem_u32(const void* p) {
    uint32_t a;
    asm("{ .reg .u64 t; cvta.to.shared.u64 t, %1; cvt.u32.u64 %0, t; }" : "=r"(a) : "l"(p));
    return a;
}
#define CP_ASYNC16(saddr, gptr) \
    asm volatile("cp.async.cg.shared.global [%0], [%1], 16;" :: "r"(saddr), "l"(gptr))
#define CP_COMMIT() asm volatile("cp.async.commit_group;" ::: "memory")
#define LDSM4(d0, d1, d2, d3, addr) \
    asm volatile("ldmatrix.sync.aligned.m8n8.x4.shared.b16 {%0,%1,%2,%3}, [%4];" \
                 : "=r"(d0), "=r"(d1), "=r"(d2), "=r"(d3) : "r"(addr))
#define MMA16816(d, a, b) \
    asm volatile("mma.sync.aligned.m16n8k16.row.col.f32.bf16.bf16.f32 " \
                 "{%0,%1,%2,%3}, {%4,%5,%6,%7}, {%8,%9}, {%0,%1,%2,%3};" \
                 : "+f"((d)[0]), "+f"((d)[1]), "+f"((d)[2]), "+f"((d)[3]) \
                 : "r"((a)[0]), "r"((a)[1]), "r"((a)[2]), "r"((a)[3]), \
                   "r"((b)[0]), "r"((b)[1]))

#define SW128(o) ((o) ^ (((o) >> 3) & 0x70))

__device__ __forceinline__ void split2(float v, __nv_bfloat16& h, __nv_bfloat16& l) {
    h = __float2bfloat16(v);
    l = __float2bfloat16(v - __bfloat162float(h));
}

// ---------------- small kernels ----------------
__global__ void compute_weights_kernel(const int* __restrict__ sel,
                                       const float* __restrict__ rw) {
    int i = threadIdx.x;
    if (i < 192) {
        int e = i / 64, b = i % 64;
        float w = 0.0f;
        if (sel[2 * b + 0] == e) w += rw[2 * b + 0];
        if (sel[2 * b + 1] == e) w += rw[2 * b + 1];
        g_w[i] = w;
    }
}

// im2col + bf16 split, 2 k-elements per thread (p even -> pairs never cross rows)
__global__ void im2col_split_kernel(const float* __restrict__ src,
                                    __nv_bfloat162* __restrict__ dh,
                                    __nv_bfloat162* __restrict__ dl,
                                    int g, int p, int s, int Kpad, int expert) {
    long long idx = (long long)blockIdx.x * blockDim.x + threadIdx.x;
    int K2 = Kpad >> 1;
    long long total = 64LL * g * g * K2;
    if (idx >= total) return;
    int k = ((int)(idx % K2)) << 1;
    long long t = idx / K2;
    int token = (int)(t % (g * g));
    int b = (int)(t / (g * g));
    if (g_w[expert * 64 + b] == 0.0f) return;
    float2 v = make_float2(0.0f, 0.0f);
    int K = 3 * p * p;
    if (k < K) {
        int ch = k / (p * p);
        int r = k % (p * p);
        int py = r / p, px = r % p;
        int gy = token / g, gx = token % g;
        v = *(const float2*)(src + (((size_t)b * 3 + ch) * s + (gy * p + py)) * s
                             + (gx * p + px));
    }
    __nv_bfloat16 h0, l0, h1, l1;
    split2(v.x, h0, l0); split2(v.y, h1, l1);
    __nv_bfloat162 ph; ph.x = h0; ph.y = h1;
    __nv_bfloat162 pl; pl.x = l0; pl.y = l1;
    dh[idx] = ph; dl[idx] = pl;
}

// E1: fused 448->336 bilinear resize + im2col + bf16 split (2 k-elems/thread)
__global__ void im2col_resize_split_kernel(const float* __restrict__ x,
                                           __nv_bfloat162* __restrict__ dh,
                                           __nv_bfloat162* __restrict__ dl) {
    long long idx = (long long)blockIdx.x * blockDim.x + threadIdx.x;
    const int K2 = 320;                       // Kpad 640 / 2
    long long total = 64LL * 576 * K2;
    if (idx >= total) return;
    int k = ((int)(idx % K2)) << 1;
    long long t = idx / K2;
    int token = (int)(t % 576);
    int b = (int)(t / 576);
    if (g_w[64 + b] == 0.0f) return;
    float v0 = 0.0f, v1 = 0.0f;
    if (k < 588) {
        int ch = k / 196;
        int r = k % 196;
        int py = r / 14, px = r % 14;
        int gy = token / 24, gx = token % 24;
        int oy = gy * 14 + py;
        int ox = gx * 14 + px;
        const float scale = 447.0f / 335.0f;
        float fy = oy * scale;
        int y0 = (int)floorf(fy); int y1 = min(y0 + 1, 447);
        float ty = fy - (float)y0;
        const float* img = x + (size_t)(b * 3 + ch) * 448 * 448;
        const float* r0p = img + (size_t)y0 * 448;
        const float* r1p = img + (size_t)y1 * 448;
#pragma unroll
        for (int j = 0; j < 2; ++j) {
            float fx = (ox + j) * scale;
            int x0 = (int)floorf(fx); int x1 = min(x0 + 1, 447);
            float tx = fx - (float)x0;
            float a0 = r0p[x0] + (r0p[x1] - r0p[x0]) * tx;
            float a1 = r1p[x0] + (r1p[x1] - r1p[x0]) * tx;
            float v = a0 + (a1 - a0) * ty;
            if (j == 0) v0 = v; else v1 = v;
        }
    }
    __nv_bfloat16 h0, l0, h1, l1;
    split2(v0, h0, l0); split2(v1, h1, l1);
    __nv_bfloat162 ph; ph.x = h0; ph.y = h1;
    __nv_bfloat162 pl; pl.x = l0; pl.y = l1;
    dh[idx] = ph; dl[idx] = pl;
}

// w[K,N] -> wT[N,Kpad] (zero pad) + bf16 split, 32x32 smem tiles
__global__ void transpose_split_kernel(const float* __restrict__ w,
                                       __nv_bfloat16* __restrict__ th,
                                       __nv_bfloat16* __restrict__ tl,
                                       int K, int N, int Kpad) {
    __shared__ float t[32][33];
    int k0 = blockIdx.y * 32, n0 = blockIdx.x * 32;
    int kk = k0 + threadIdx.y, nn = n0 + threadIdx.x;
    t[threadIdx.y][threadIdx.x] = (kk < K && nn < N) ? w[(size_t)kk * N + nn] : 0.0f;
    __syncthreads();
    int on = n0 + threadIdx.y, ok = k0 + threadIdx.x;
    if (on < N && ok < Kpad) {
        __nv_bfloat16 h, l; split2(t[threadIdx.x][threadIdx.y], h, l);
        th[(size_t)on * Kpad + ok] = h;
        tl[(size_t)on * Kpad + ok] = l;
    }
}

// feature grid resize g x g -> 32 x 32 with bf16 split output (2-wide)
__global__ void feat_resize_split_kernel(const float* __restrict__ in,
                                         __nv_bfloat16* __restrict__ oh,
                                         __nv_bfloat16* __restrict__ ol,
                                         int g, int c, int expert) {
    int token = blockIdx.x & 1023;
    int b = blockIdx.x >> 10;
    if (g_w[expert * 64 + b] == 0.0f) return;
    int oy = token >> 5, ox = token & 31;
    float scale = (float)(g - 1) / 31.0f;
    float fy = oy * scale, fx = ox * scale;
    int y0 = (int)floorf(fy), x0 = (int)floorf(fx);
    int y1 = min(y0 + 1, g - 1), x1 = min(x0 + 1, g - 1);
    float ty = fy - y0, tx = fx - x0;
    float w00 = (1.f - ty) * (1.f - tx), w01 = (1.f - ty) * tx;
    float w10 = ty * (1.f - tx),         w11 = ty * tx;
    const float* base = in + (size_t)b * g * g * c;
    const float2* p00 = (const float2*)(base + (size_t)(y0 * g + x0) * c);
    const float2* p01 = (const float2*)(base + (size_t)(y0 * g + x1) * c);
    const float2* p10 = (const float2*)(base + (size_t)(y1 * g + x0) * c);
    const float2* p11 = (const float2*)(base + (size_t)(y1 * g + x1) * c);
    size_t rowOff = ((size_t)b * 1024 + token) * c;
    __nv_bfloat162* ph2 = (__nv_bfloat162*)(oh + rowOff);
    __nv_bfloat162* pl2 = (__nv_bfloat162*)(ol + rowOff);
    int c2 = c >> 1;
    for (int i = threadIdx.x; i < c2; i += blockDim.x) {
        float2 a = p00[i], bq = p01[i], cq = p10[i], d = p11[i];
        float v0 = w00 * a.x + w01 * bq.x + w10 * cq.x + w11 * d.x;
        float v1 = w00 * a.y + w01 * bq.y + w10 * cq.y + w11 * d.y;
        __nv_bfloat16 h0, l0, h1, l1;
        split2(v0, h0, l0); split2(v1, h1, l1);
        __nv_bfloat162 ph; ph.x = h0; ph.y = h1;
        __nv_bfloat162 pl; pl.x = l0; pl.y = l1;
        ph2[i] = ph; pl2[i] = pl;
    }
}

// ===========================================================================
// mma.sync GEMM: D[128x128] = (Ah+Al)[128,K] @ (Bh+Bl)[128,K]^T (3 passes).
// SW128 smem stages of BK=64 (Ah|Al|Bh|Bl @ 16KB each), 3-stage pipeline.
// 512 threads, 16 warps, warp tile 32x32 (warp grid 4x4).
// MODE 0: tower -> split bf16 (Ch/Cl, ldc)    MODE 1: tower -> fp32 (C, ldc)
// MODE 2: proj  -> C[row*1024+col] += w_b * (v + bias)
// ===========================================================================
#define STAGE_BYTES 65536
#define NSTAGE 3

__device__ __forceinline__ void load_stage(
    uint32_t sb, const __nv_bfloat16* Ah, const __nv_bfloat16* Al,
    const __nv_bfloat16* Bh, const __nv_bfloat16* Bl,
    int rowStart, int colStart, int Kpad, int k0, int tid) {
#pragma unroll 8
    for (int c = tid; c < 4096; c += 512) {
        int half = (c >> 10) & 1;
        int cc = c & 1023;
        int r = cc >> 3, kc = cc & 7;
        const __nv_bfloat16* gp;
        uint32_t so;
        if (c < 2048) {
            gp = (half ? Al : Ah) + (size_t)(rowStart + r) * Kpad + k0 + kc * 8;
            so = sb + half * 16384 + SW128(r * 128 + kc * 16);
        } else {
            gp = (half ? Bl : Bh) + (size_t)(colStart + r) * Kpad + k0 + kc * 8;
            so = sb + 32768 + half * 16384 + SW128(r * 128 + kc * 16);
        }
        CP_ASYNC16(so, (const void*)gp);
    }
}

template <int MODE>
__global__ __launch_bounds__(512, 1) void gemm_mma(
    int Kpad, int tps, int expert,
    const __nv_bfloat16* __restrict__ Ah, const __nv_bfloat16* __restrict__ Al,
    const __nv_bfloat16* __restrict__ Bh, const __nv_bfloat16* __restrict__ Bl,
    const float* __restrict__ bias,
    float* __restrict__ C, __nv_bfloat16* __restrict__ Ch, __nv_bfloat16* __restrict__ Cl,
    int ldc) {
    const int tid = threadIdx.x;
    const int wid = tid >> 5, lane = tid & 31;
    const int rowStart = blockIdx.y * 128;
    const int colStart = blockIdx.x * 128;

    // routing skip: all samples covered by this M-block unrouted -> no work
    {
        int bLo = rowStart / tps, bHi = (rowStart + 127) / tps;
        bool any = false;
        for (int b = bLo; b <= bHi; ++b) any = any || (g_w[expert * 64 + b] != 0.0f);
        if (!any) return;
    }

    extern __shared__ __align__(1024) char smem[];
    const uint32_t sb0 = smem_u32(smem);
    const int wm = (wid >> 2) * 32, wn = (wid & 3) * 32;

    float acc[2][4][4];
#pragma unroll
    for (int i = 0; i < 2; ++i)
#pragma unroll
        for (int j = 0; j < 4; ++j)
#pragma unroll
            for (int r = 0; r < 4; ++r) acc[i][j][r] = 0.0f;

    const int KBn = Kpad >> 6;
    const int arow = wm + (lane & 15);
    const int alo  = lane >> 4;
    const int bmat = lane >> 3;
    const int brow = ((bmat >> 1) << 3) + (lane & 7);
    const int bko  = bmat & 1;

    load_stage(sb0, Ah, Al, Bh, Bl, rowStart, colStart, Kpad, 0, tid);
    CP_COMMIT();
    if (KBn > 1) {
        load_stage(sb0 + STAGE_BYTES, Ah, Al, Bh, Bl, rowStart, colStart, Kpad, 64, tid);
        CP_COMMIT();
    }

    int stage = 0;
    for (int kb = 0; kb < KBn; ++kb) {
        if (kb + 1 < KBn)
            asm volatile("cp.async.wait_group 1;" ::: "memory");
        else
            asm volatile("cp.async.wait_group 0;" ::: "memory");
        __syncthreads();

        const uint32_t sb = sb0 + stage * STAGE_BYTES;
#pragma unroll
        for (int kk = 0; kk < 4; ++kk) {
            uint32_t ah[2][4], al[2][4], bh[4][2], bl[4][2];
#pragma unroll
            for (int mi = 0; mi < 2; ++mi) {
                uint32_t off = SW128((arow + 16 * mi) * 128 + (kk * 2 + alo) * 16);
                LDSM4(ah[mi][0], ah[mi][1], ah[mi][2], ah[mi][3], sb + off);
                LDSM4(al[mi][0], al[mi][1], al[mi][2], al[mi][3], sb + 16384 + off);
            }
#pragma unroll
            for (int p = 0; p < 2; ++p) {
                uint32_t off = SW128((wn + p * 16 + brow) * 128 + (kk * 2 + bko) * 16);
                LDSM4(bh[2 * p][0], bh[2 * p][1], bh[2 * p + 1][0], bh[2 * p + 1][1],
                      sb + 32768 + off);
                LDSM4(bl[2 * p][0], bl[2 * p][1], bl[2 * p + 1][0], bl[2 * p + 1][1],
                      sb + 49152 + off);
            }
            // Pass-major emission: each accumulator is touched once per pass,
            // so dependent MMAs on the same acc are 8 independent MMAs apart.
#pragma unroll
            for (int mi = 0; mi < 2; ++mi)
#pragma unroll
                for (int nj = 0; nj < 4; ++nj)
                    MMA16816(acc[mi][nj], ah[mi], bh[nj]);
#pragma unroll
            for (int mi = 0; mi < 2; ++mi)
#pragma unroll
                for (int nj = 0; nj < 4; ++nj)
                    MMA16816(acc[mi][nj], ah[mi], bl[nj]);
#pragma unroll
            for (int mi = 0; mi < 2; ++mi)
#pragma unroll
                for (int nj = 0; nj < 4; ++nj)
                    MMA16816(acc[mi][nj], al[mi], bh[nj]);
        }

        if (kb + 2 < KBn) {
            int ns = stage + 2; if (ns >= NSTAGE) ns -= NSTAGE;
            load_stage(sb0 + ns * STAGE_BYTES, Ah, Al, Bh, Bl,
                       rowStart, colStart, Kpad, (kb + 2) << 6, tid);
            CP_COMMIT();
        }
        if (++stage == NSTAGE) stage = 0;
    }

    // -------- epilogue straight from registers --------
    const int tq = lane >> 2;            // row within 8
    const int tr2 = (lane & 3) * 2;      // col pair
    if (MODE == 2) {
        float w = g_w[expert * 64 + (rowStart >> 10)];
#pragma unroll
        for (int nj = 0; nj < 4; ++nj) {
            int col = colStart + wn + nj * 8 + tr2;
            float b0 = bias[col], b1 = bias[col + 1];
#pragma unroll
            for (int mi = 0; mi < 2; ++mi) {
                int row0 = rowStart + wm + mi * 16 + tq;
                float* p0 = C + (size_t)row0 * 1024 + col;
                float* p1 = p0 + 8 * 1024;
                p0[0] += w * (acc[mi][nj][0] + b0);
                p0[1] += w * (acc[mi][nj][1] + b1);
                p1[0] += w * (acc[mi][nj][2] + b0);
                p1[1] += w * (acc[mi][nj][3] + b1);
            }
        }
    } else if (MODE == 0) {
#pragma unroll
        for (int nj = 0; nj < 4; ++nj) {
            int col = colStart + wn + nj * 8 + tr2;
            float b0 = bias[col], b1 = bias[col + 1];
#pragma unroll
            for (int mi = 0; mi < 2; ++mi) {
                int row0 = rowStart + wm + mi * 16 + tq;
#pragma unroll
                for (int h = 0; h < 2; ++h) {
                    int row = row0 + h * 8;
                    float v0 = acc[mi][nj][2 * h + 0] + b0;
                    float v1 = acc[mi][nj][2 * h + 1] + b1;
                    __nv_bfloat16 h0, l0, h1, l1;
                    split2(v0, h0, l0); split2(v1, h1, l1);
                    __nv_bfloat162 ph; ph.x = h0; ph.y = h1;
                    __nv_bfloat162 pl; pl.x = l0; pl.y = l1;
                    *(__nv_bfloat162*)(Ch + (size_t)row * ldc + col) = ph;
                    *(__nv_bfloat162*)(Cl + (size_t)row * ldc + col) = pl;
                }
            }
        }
    } else {
#pragma unroll
        for (int nj = 0; nj < 4; ++nj) {
            int col = colStart + wn + nj * 8 + tr2;
            float b0 = bias[col], b1 = bias[col + 1];
#pragma unroll
            for (int mi = 0; mi < 2; ++mi) {
                int row0 = rowStart + wm + mi * 16 + tq;
                float* p0 = C + (size_t)row0 * ldc + col;
                float* p1 = p0 + (size_t)8 * ldc;
                p0[0] = acc[mi][nj][0] + b0;
                p0[1] = acc[mi][nj][1] + b1;
                p1[0] = acc[mi][nj][2] + b0;
                p1[1] = acc[mi][nj][3] + b1;
            }
        }
    }
}

// ===========================================================================
extern "C" void kernel_launch(void* const* d_in, const int* in_sizes, int n_in,
                              void* d_out, int out_size) {
    const float* x   = (const float*)d_in[0];
    const int*   sel = (const int*)d_in[1];
    const float* rw  = (const float*)d_in[2];
    const float* wt0 = (const float*)d_in[3];
    const float* bt0 = (const float*)d_in[4];
    const float* wp0 = (const float*)d_in[5];
    const float* bp0 = (const float*)d_in[6];
    const float* wt1 = (const float*)d_in[7];
    const float* bt1 = (const float*)d_in[8];
    const float* wp1 = (const float*)d_in[9];
    const float* bp1 = (const float*)d_in[10];
    const float* wt2 = (const float*)d_in[11];
    const float* bt2 = (const float*)d_in[12];
    const float* wp2 = (const float*)d_in[13];
    const float* bp2 = (const float*)d_in[14];
    float* out = (float*)d_out;

    float* pfeat;
    __nv_bfloat16 *pph, *ppl, *pfh, *pfl, *pwh, *pwl;
    cudaGetSymbolAddress((void**)&pph, g_patch_h);
    cudaGetSymbolAddress((void**)&ppl, g_patch_l);
    cudaGetSymbolAddress((void**)&pfh, g_featA_h);
    cudaGetSymbolAddress((void**)&pfl, g_featA_l);
    cudaGetSymbolAddress((void**)&pfeat, g_feat);
    cudaGetSymbolAddress((void**)&pwh, g_wT_h);
    cudaGetSymbolAddress((void**)&pwl, g_wT_l);

    const int SMEM = NSTAGE * STAGE_BYTES;   // 196608
    cudaFuncSetAttribute(gemm_mma<0>, cudaFuncAttributeMaxDynamicSharedMemorySize, SMEM);
    cudaFuncSetAttribute(gemm_mma<1>, cudaFuncAttributeMaxDynamicSharedMemorySize, SMEM);
    cudaFuncSetAttribute(gemm_mma<2>, cudaFuncAttributeMaxDynamicSharedMemorySize, SMEM);

    compute_weights_kernel<<<1, 192>>>(sel, rw);
    cudaMemsetAsync(d_out, 0, (size_t)out_size * sizeof(float), 0);

    // ---------------- Expert 0: g=32 c=1024, Ktower 588->640 ----------------
    {
        long long tot2 = 64LL * 1024 * 320;
        im2col_split_kernel<<<(unsigned)((tot2 + 255) / 256), 256>>>(
            x, (__nv_bfloat162*)pph, (__nv_bfloat162*)ppl, 32, 14, 448, 640, 0);
        transpose_split_kernel<<<dim3(32, 20), dim3(32, 32)>>>(wt0, pwh, pwl, 588, 1024, 640);
        gemm_mma<0><<<dim3(8, 512), 512, SMEM>>>(640, 1024, 0,
            pph, ppl, pwh, pwl, bt0, nullptr, pfh, pfl, 1024);
        transpose_split_kernel<<<dim3(32, 32), dim3(32, 32)>>>(wp0, pwh, pwl, 1024, 1024, 1024);
        gemm_mma<2><<<dim3(8, 512), 512, SMEM>>>(1024, 1024, 0,
            pfh, pfl, pwh, pwl, bp0, out, nullptr, nullptr, 1024);
    }

    // ---------------- Expert 1: g=24 c=768, fused resize+im2col ----------------
    {
        long long tot2 = 64LL * 576 * 320;
        im2col_resize_split_kernel<<<(unsigned)((tot2 + 255) / 256), 256>>>(
            x, (__nv_bfloat162*)pph, (__nv_bfloat162*)ppl);
        transpose_split_kernel<<<dim3(24, 20), dim3(32, 32)>>>(wt1, pwh, pwl, 588, 768, 640);
        gemm_mma<1><<<dim3(6, 288), 512, SMEM>>>(640, 576, 1,
            pph, ppl, pwh, pwl, bt1, pfeat, nullptr, nullptr, 768);
        feat_resize_split_kernel<<<64 * 1024, 128>>>(pfeat, pfh, pfl, 24, 768, 1);
        transpose_split_kernel<<<dim3(32, 24), dim3(32, 32)>>>(wp1, pwh, pwl, 768, 1024, 768);
        gemm_mma<2><<<dim3(8, 512), 512, SMEM>>>(768, 1024, 1,
            pfh, pfl, pwh, pwl, bp1, out, nullptr, nullptr, 1024);
    }

    // ---------------- Expert 2: g=14 c=1152, Ktower=3072 ----------------
    {
        long long tot2 = 64LL * 196 * 1536;
        im2col_split_kernel<<<(unsigned)((tot2 + 255) / 256), 256>>>(
            x, (__nv_bfloat162*)pph, (__nv_bfloat162*)ppl, 14, 32, 448, 3072, 2);
        transpose_split_kernel<<<dim3(36, 96), dim3(32, 32)>>>(wt2, pwh, pwl, 3072, 1152, 3072);
        gemm_mma<1><<<dim3(9, 98), 512, SMEM>>>(3072, 196, 2,
            pph, ppl, pwh, pwl, bt2, pfeat, nullptr, nullptr, 1152);
        feat_resize_split_kernel<<<64 * 1024, 128>>>(pfeat, pfh, pfl, 14, 1152, 2);
        transpose_split_kernel<<<dim3(32, 36), dim3(32, 32)>>>(wp2, pwh, pwl, 1152, 1024, 1152);
        gemm_mma<2><<<dim3(8, 512), 512, SMEM>>>(1152, 1024, 2,
            pfh, pfl, pwh, pwl, bp2, out, nullptr, nullptr, 1024);
    }
}